// round 5
// baseline (speedup 1.0000x reference)
#include <cuda_runtime.h>
#include <cuda_bf16.h>
#include <cstdint>
#include <cstddef>

#define T_DIM  32
#define K2     512
#define KD     262144
#define THRESH 0.2f

#define OTILE  128
#define KSPLIT 37
#define KB     32                      // fp32 k per slab
#define SLABS_TOT (KD / KB)            // 8192
#define SBASE (SLABS_TOT / KSPLIT)     // 221
#define SREM  (SLABS_TOT - SBASE * KSPLIT)  // 15

// per-buffer smem: W 128 rows x 128B (hi|lo chunks), R 32 rows x 128B
#define WBYTES (OTILE * 128)           // 16384
#define RBASE  WBYTES
#define BUFBYTES (WBYTES + T_DIM * 128)  // 20480

__device__ float g_partial[(size_t)KSPLIT * T_DIM * K2];  // [sp][t][o]
__device__ float g_dot[T_DIM * K2];

// ---------------- helpers ----------------
__device__ __forceinline__ uint32_t smem_u32(const void* p) {
    uint32_t a;
    asm("{ .reg .u64 t; cvta.to.shared.u64 t, %1; cvt.u32.u64 %0, t; }"
        : "=r"(a) : "l"(p));
    return a;
}
__device__ __forceinline__ void ldsm_x4(uint32_t* r, uint32_t addr) {
    asm volatile("ldmatrix.sync.aligned.m8n8.x4.shared.b16 {%0,%1,%2,%3}, [%4];"
                 : "=r"(r[0]), "=r"(r[1]), "=r"(r[2]), "=r"(r[3]) : "r"(addr));
}
// NON-transposed x2: rec tile is stored [t][k]; B fragment pairs must run
// along k, which non-trans ldmatrix provides directly.
__device__ __forceinline__ void ldsm_x2(uint32_t* r, uint32_t addr) {
    asm volatile("ldmatrix.sync.aligned.m8n8.x2.shared.b16 {%0,%1}, [%2];"
                 : "=r"(r[0]), "=r"(r[1]) : "r"(addr));
}
__device__ __forceinline__ void mma_bf16(float* c, const uint32_t* a, const uint32_t* b) {
    asm volatile("mma.sync.aligned.m16n8k16.row.col.f32.bf16.bf16.f32 "
                 "{%0,%1,%2,%3}, {%4,%5,%6,%7}, {%8,%9}, {%0,%1,%2,%3};"
                 : "+f"(c[0]), "+f"(c[1]), "+f"(c[2]), "+f"(c[3])
                 : "r"(a[0]), "r"(a[1]), "r"(a[2]), "r"(a[3]),
                   "r"(b[0]), "r"(b[1]));
}
// split float pair into hi/lo bf16x2 words
__device__ __forceinline__ void cvt2(float a, float b, uint32_t& h, uint32_t& l) {
    __nv_bfloat162 hb = __floats2bfloat162_rn(a, b);
    float2 hf = __bfloat1622float2(hb);
    __nv_bfloat162 lb = __floats2bfloat162_rn(a - hf.x, b - hf.y);
    h = *reinterpret_cast<uint32_t*>(&hb);
    l = *reinterpret_cast<uint32_t*>(&lb);
}

// ---------------------------------------------------------------------------
// HMMA GEMM: partial[sp][t][o] = sum_{k in split} rec[t][k] * w[o][k]
// bf16 3-product split (hh + hl + lh) accumulated in fp32
// ---------------------------------------------------------------------------
__global__ void __launch_bounds__(256, 1)
gemm_hmma(const float* __restrict__ rec, const float* __restrict__ wgt)
{
    __shared__ __align__(16) char sm[2][BUFBYTES];

    const int tid = threadIdx.x;
    const int wid = tid >> 5;
    const int lid = tid & 31;
    const int ot  = blockIdx.x;            // 0..3
    const int sp  = blockIdx.y;            // 0..36
    const int obase = ot * OTILE;

    const int s_begin = sp * SBASE + (sp < SREM ? sp : SREM);
    const int s_count = SBASE + (sp < SREM ? 1 : 0);

    const uint32_t base0 = smem_u32(&sm[0][0]);

    // ---- staging maps ----
    const int w_row = tid >> 1;            // 0..127
    const int w_kh  = tid & 1;             // k half (0..15 / 16..31)
    const int w_xr  = w_row & 7;
    const float* wptr = wgt + (size_t)(obase + w_row) * KD
                        + (size_t)s_begin * KB + w_kh * 16;
    const int r_row = (tid >> 1) & 31;     // threads 0..63 active
    const int r_kh  = tid & 1;
    const int r_xr  = r_row & 7;
    const float* rptr = rec + (size_t)r_row * KD
                        + (size_t)s_begin * KB + r_kh * 16;
    const bool r_act = (tid < 64);

    // ---- compute-side lane constants ----
    const int ob_w = (wid >> 1) * 32;      // warp o offset in tile
    const int tb_w = (wid & 1) * 16;       // warp t offset
    const int a_row = ob_w + (lid & 15);
    const int a_sel = lid >> 4;            // 0/1 (k chunk within 16-step)
    const int a_x   = lid & 7;
    const uint32_t a_off = (uint32_t)a_row * 128;
    const int b_row = tb_w + (lid & 7);
    const int b_sel = (lid >> 3) & 1;
    const int b_x   = lid & 7;
    const uint32_t b_off = RBASE + (uint32_t)b_row * 128;

    float acc[2][2][4];
#pragma unroll
    for (int mt = 0; mt < 2; mt++)
#pragma unroll
        for (int nt = 0; nt < 2; nt++)
#pragma unroll
            for (int i = 0; i < 4; i++) acc[mt][nt][i] = 0.0f;

    float4 wv[4], rv[4];

#define LOAD_SLAB(S)                                                          \
    {   const size_t ko = (size_t)(S) * KB;                                    \
        _Pragma("unroll") for (int j = 0; j < 4; j++)                          \
            wv[j] = *reinterpret_cast<const float4*>(wptr + ko + j * 4);       \
        if (r_act) {                                                           \
            _Pragma("unroll") for (int j = 0; j < 4; j++)                      \
                rv[j] = *reinterpret_cast<const float4*>(rptr + ko + j * 4);   \
        } }

#define STORE_SLAB(B)                                                          \
    {   char* wb = &sm[B][0] + (size_t)w_row * 128;                            \
        _Pragma("unroll") for (int q = 0; q < 2; q++) {                        \
            uint4 hc, lc;                                                      \
            cvt2(wv[2*q].x,   wv[2*q].y,   hc.x, lc.x);                        \
            cvt2(wv[2*q].z,   wv[2*q].w,   hc.y, lc.y);                        \
            cvt2(wv[2*q+1].x, wv[2*q+1].y, hc.z, lc.z);                        \
            cvt2(wv[2*q+1].z, wv[2*q+1].w, hc.w, lc.w);                        \
            const int lch = w_kh * 2 + q;                                      \
            *reinterpret_cast<uint4*>(wb + ((lch ^ w_xr) * 16)) = hc;          \
            *reinterpret_cast<uint4*>(wb + (((lch + 4) ^ w_xr) * 16)) = lc;    \
        }                                                                      \
        if (r_act) {                                                           \
            char* rb = &sm[B][0] + RBASE + (size_t)r_row * 128;                \
            _Pragma("unroll") for (int q = 0; q < 2; q++) {                    \
                uint4 hc, lc;                                                  \
                cvt2(rv[2*q].x,   rv[2*q].y,   hc.x, lc.x);                    \
                cvt2(rv[2*q].z,   rv[2*q].w,   hc.y, lc.y);                    \
                cvt2(rv[2*q+1].x, rv[2*q+1].y, hc.z, lc.z);                    \
                cvt2(rv[2*q+1].z, rv[2*q+1].w, hc.w, lc.w);                    \
                const int lch = r_kh * 2 + q;                                  \
                *reinterpret_cast<uint4*>(rb + ((lch ^ r_xr) * 16)) = hc;      \
                *reinterpret_cast<uint4*>(rb + (((lch + 4) ^ r_xr) * 16)) = lc;\
            } } }

    // prologue
    LOAD_SLAB(0)
    STORE_SLAB(0)
    __syncthreads();

    for (int s = 0; s < s_count; s++) {
        const int b = s & 1;
        const bool more = (s + 1 < s_count);
        if (more) LOAD_SLAB(s + 1)

        const uint32_t bufb = base0 + (uint32_t)b * BUFBYTES;
#pragma unroll
        for (int ks = 0; ks < 2; ks++) {
            const int c0 = ks * 2;
            uint32_t Ah[2][4], Al[2][4], Bh[2][2], Bl[2][2];
#pragma unroll
            for (int mt = 0; mt < 2; mt++) {
                const uint32_t rowad = bufb + a_off + (uint32_t)mt * 16 * 128;
                ldsm_x4(Ah[mt], rowad + (uint32_t)(((c0 + a_sel) ^ a_x) * 16));
                ldsm_x4(Al[mt], rowad + (uint32_t)(((c0 + a_sel + 4) ^ a_x) * 16));
            }
#pragma unroll
            for (int nt = 0; nt < 2; nt++) {
                const uint32_t rowad = bufb + b_off + (uint32_t)nt * 8 * 128;
                ldsm_x2(Bh[nt], rowad + (uint32_t)(((c0 + b_sel) ^ b_x) * 16));
                ldsm_x2(Bl[nt], rowad + (uint32_t)(((c0 + b_sel + 4) ^ b_x) * 16));
            }
#pragma unroll
            for (int mt = 0; mt < 2; mt++)
#pragma unroll
                for (int nt = 0; nt < 2; nt++) {
                    mma_bf16(acc[mt][nt], Ah[mt], Bh[nt]);  // hh
                    mma_bf16(acc[mt][nt], Ah[mt], Bl[nt]);  // hl
                    mma_bf16(acc[mt][nt], Al[mt], Bh[nt]);  // lh
                }
        }

        if (more) STORE_SLAB(b ^ 1)
        __syncthreads();
    }

    // epilogue: scatter accumulators to g_partial[sp][t][o]
#pragma unroll
    for (int mt = 0; mt < 2; mt++)
#pragma unroll
        for (int nt = 0; nt < 2; nt++) {
            const int o0 = obase + ob_w + mt * 16 + (lid >> 2);
            const int t0 = tb_w + nt * 8 + (lid & 3) * 2;
#pragma unroll
            for (int c = 0; c < 4; c++) {
                const int o = o0 + ((c >> 1) ? 8 : 0);
                const int t = t0 + (c & 1);
                g_partial[((size_t)sp * T_DIM + t) * K2 + o] = acc[mt][nt][c];
            }
        }
}

// ---------------------------------------------------------------------------
// deterministic split-K reduction
// ---------------------------------------------------------------------------
__global__ void __launch_bounds__(512) reduce_kernel()
{
    const int t = blockIdx.x;
    const int o = threadIdx.x;
    const size_t stride = (size_t)T_DIM * K2;
    const size_t idx = (size_t)t * K2 + o;
    float s = 0.0f;
#pragma unroll
    for (int sp = 0; sp < KSPLIT; sp++)
        s += g_partial[(size_t)sp * stride + idx];
    g_dot[t * K2 + o] = s;
}

// ---------------------------------------------------------------------------
// post: threshold -> first-spike -> totals -> 8-round k-WTA -> binary output
// ---------------------------------------------------------------------------
__global__ void __launch_bounds__(512) post_kernel(float* __restrict__ outp)
{
    const int o = threadIdx.x;

    unsigned mask = 0;
    int cnt = 0;
#pragma unroll
    for (int t = 0; t < T_DIM; t++) {
        const float v = g_dot[t * K2 + o];
        if (v >= THRESH) { cnt++; mask |= (1u << t); }
    }
    int first = T_DIM - cnt;
    if (first > T_DIM - 1) first = T_DIM - 1;
    const float fv    = g_dot[first * K2 + o];
    const float value = (fv < THRESH) ? 0.0f : fv;
    const float cand  = (cnt > 0) ? value : 0.0f;

    __shared__ float smx[K2];
    smx[o] = cand;
    __syncthreads();
    for (int s = K2 / 2; s > 0; s >>= 1) {
        if (o < s) smx[o] = fmaxf(smx[o], smx[o + s]);
        __syncthreads();
    }
    const float voff = smx[0] * (float)T_DIM;
    __syncthreads();

    __shared__ float tots[K2];
    __shared__ unsigned long long pk[K2];
    __shared__ unsigned char sel[K2];
    tots[o] = (cnt > 0) ? (float)cnt * (value + voff) : 0.0f;
    sel[o]  = 0;
    __syncthreads();

    for (int r = 0; r < 8; r++) {
        pk[o] = ((unsigned long long)__float_as_uint(tots[o]) << 32)
                | (unsigned)(K2 - 1 - o);
        __syncthreads();
        for (int s = K2 / 2; s > 0; s >>= 1) {
            if (o < s) { unsigned long long b = pk[o + s]; if (b > pk[o]) pk[o] = b; }
            __syncthreads();
        }
        if (o == 0) {
            const int idx = (K2 - 1) - (int)(unsigned)(pk[0] & 0xffffffffULL);
            if (tots[idx] != 0.0f) sel[idx] = 1;
            tots[idx] = 0.0f;
        }
        __syncthreads();
    }

#pragma unroll
    for (int t = 0; t < T_DIM; t++) {
        outp[t * K2 + o] = (sel[o] && ((mask >> t) & 1u)) ? 1.0f : 0.0f;
    }
}

// ---------------------------------------------------------------------------
extern "C" void kernel_launch(void* const* d_in, const int* in_sizes, int n_in,
                              void* d_out, int out_size)
{
    const float* rec = (const float*)d_in[0];   // (32,1,64,4096)
    const float* wgt = (const float*)d_in[1];   // (512,1,64,4096)
    if (n_in >= 2 && in_sizes[0] > in_sizes[1]) {
        const float* tmp = rec; rec = wgt; wgt = tmp;
    }
    float* outp = (float*)d_out;

    gemm_hmma<<<dim3(4, KSPLIT), 256>>>(rec, wgt);
    reduce_kernel<<<T_DIM, K2>>>();
    post_kernel<<<1, K2>>>(outp);
}

// round 6
// speedup vs baseline: 2.0471x; 2.0471x over previous
#include <cuda_runtime.h>
#include <cuda_bf16.h>
#include <cstdint>
#include <cstddef>

#define T_DIM  32
#define K2     512
#define KD     262144
#define THRESH 0.2f

#define KSPLIT 74
#define STEPS_TOT (KD / 16)                    // 16384 16-k steps
#define SBASE (STEPS_TOT / KSPLIT)             // 221
#define SREM  (STEPS_TOT - SBASE * KSPLIT)     // 30

__device__ float g_partial[(size_t)KSPLIT * T_DIM * K2];  // [sp][t][o]
__device__ float g_dot[T_DIM * K2];

// ---------------- helpers ----------------
__device__ __forceinline__ void mma_bf16(float* c, const uint32_t* a, const uint32_t* b) {
    asm volatile("mma.sync.aligned.m16n8k16.row.col.f32.bf16.bf16.f32 "
                 "{%0,%1,%2,%3}, {%4,%5,%6,%7}, {%8,%9}, {%0,%1,%2,%3};"
                 : "+f"(c[0]), "+f"(c[1]), "+f"(c[2]), "+f"(c[3])
                 : "r"(a[0]), "r"(a[1]), "r"(a[2]), "r"(a[3]),
                   "r"(b[0]), "r"(b[1]));
}
// split float pair into hi/lo bf16x2 words (hi = rn(f), lo = rn(f - hi))
__device__ __forceinline__ void cvt2(float a, float b, uint32_t& h, uint32_t& l) {
    __nv_bfloat162 hb = __floats2bfloat162_rn(a, b);
    float2 hf = __bfloat1622float2(hb);
    __nv_bfloat162 lb = __floats2bfloat162_rn(a - hf.x, b - hf.y);
    h = *reinterpret_cast<uint32_t*>(&hb);
    l = *reinterpret_cast<uint32_t*>(&lb);
}

// ---------------------------------------------------------------------------
// Direct-from-gmem HMMA GEMM (no smem, no syncs):
//   partial[sp][t][o] = sum_{k in split} rec[t][k] * w[o][k]
// warp = 16 o-rows x 32 t (4 n-tiles); bf16 3-product split in fp32 acc.
// A-fragments (W) and B-fragments (rec) loaded as float2 per documented
// mma.m16n8k16 lane maps, converted in registers.
// ---------------------------------------------------------------------------
__global__ void __launch_bounds__(256, 2)
gemm_direct(const float* __restrict__ rec, const float* __restrict__ wgt)
{
    const int tid = threadIdx.x;
    const int wid = tid >> 5;
    const int lid = tid & 31;
    const int g   = lid >> 2;          // group id (0..7)
    const int tig = lid & 3;           // thread-in-group
    const int ot  = blockIdx.x;        // 0..3
    const int sp  = blockIdx.y;        // 0..73

    const int obase = ot * 128;
    const int orow  = obase + wid * 16 + g;

    const int s_begin = sp * SBASE + (sp < SREM ? sp : SREM);
    const int s_count = SBASE + (sp < SREM ? 1 : 0);
    const size_t k0 = (size_t)s_begin * 16;

    // A (W): lane covers rows {orow, orow+8}, cols {2tig, 2tig+1, +8}
    const float* pA0 = wgt + (size_t)orow * KD + k0 + 2 * tig;
    const float* pA1 = pA0 + 8 * (size_t)KD;
    // B (rec): for n-tile nt, lane covers col(t) = nt*8+g, k rows {2tig,2tig+1,+8}
    const float* pB[4];
#pragma unroll
    for (int nt = 0; nt < 4; nt++)
        pB[nt] = rec + (size_t)(nt * 8 + g) * KD + k0 + 2 * tig;

    float acc[4][4];
#pragma unroll
    for (int nt = 0; nt < 4; nt++)
#pragma unroll
        for (int i = 0; i < 4; i++) acc[nt][i] = 0.0f;

    float2 Af[2][4], Bf[2][8];

#define LOAD_STEP(ST, S)                                                      \
    {   const size_t off = (size_t)(S) * 16;                                   \
        Af[ST][0] = *reinterpret_cast<const float2*>(pA0 + off);               \
        Af[ST][1] = *reinterpret_cast<const float2*>(pA1 + off);               \
        Af[ST][2] = *reinterpret_cast<const float2*>(pA0 + off + 8);           \
        Af[ST][3] = *reinterpret_cast<const float2*>(pA1 + off + 8);           \
        _Pragma("unroll") for (int nt = 0; nt < 4; nt++) {                     \
            Bf[ST][nt * 2]     = *reinterpret_cast<const float2*>(pB[nt] + off);     \
            Bf[ST][nt * 2 + 1] = *reinterpret_cast<const float2*>(pB[nt] + off + 8); \
        } }

#define COMPUTE_STEP(ST)                                                      \
    {   uint32_t Ah[4], Al[4];                                                 \
        _Pragma("unroll") for (int i = 0; i < 4; i++)                          \
            cvt2(Af[ST][i].x, Af[ST][i].y, Ah[i], Al[i]);                      \
        _Pragma("unroll") for (int nt = 0; nt < 4; nt++) {                     \
            uint32_t Bh[2], Bl[2];                                             \
            cvt2(Bf[ST][nt*2].x,   Bf[ST][nt*2].y,   Bh[0], Bl[0]);            \
            cvt2(Bf[ST][nt*2+1].x, Bf[ST][nt*2+1].y, Bh[1], Bl[1]);            \
            mma_bf16(acc[nt], Ah, Bh);                                         \
            mma_bf16(acc[nt], Ah, Bl);                                         \
            mma_bf16(acc[nt], Al, Bh);                                         \
        } }

    LOAD_STEP(0, 0)
#pragma unroll 2
    for (int s = 0; s < s_count; s++) {
        const int st = s & 1;
        if (s + 1 < s_count) LOAD_STEP(st ^ 1, s + 1)
        COMPUTE_STEP(st)
    }

    // epilogue: C frag c0=(g,2tig) c1=(g,2tig+1) c2=(g+8,2tig) c3=(g+8,2tig+1)
#pragma unroll
    for (int nt = 0; nt < 4; nt++)
#pragma unroll
        for (int c = 0; c < 4; c++) {
            const int o = orow + ((c >> 1) ? 8 : 0);
            const int t = nt * 8 + 2 * tig + (c & 1);
            g_partial[((size_t)sp * T_DIM + t) * K2 + o] = acc[nt][c];
        }
}

// ---------------------------------------------------------------------------
// deterministic split-K reduction
// ---------------------------------------------------------------------------
__global__ void __launch_bounds__(512) reduce_kernel()
{
    const int t = blockIdx.x;
    const int o = threadIdx.x;
    const size_t stride = (size_t)T_DIM * K2;
    const size_t idx = (size_t)t * K2 + o;
    float s = 0.0f;
#pragma unroll
    for (int sp = 0; sp < KSPLIT; sp++)
        s += g_partial[(size_t)sp * stride + idx];
    g_dot[t * K2 + o] = s;
}

// ---------------------------------------------------------------------------
// post: threshold -> first-spike -> totals -> 8-round k-WTA -> binary output
// ---------------------------------------------------------------------------
__global__ void __launch_bounds__(512) post_kernel(float* __restrict__ outp)
{
    const int o = threadIdx.x;

    unsigned mask = 0;
    int cnt = 0;
#pragma unroll
    for (int t = 0; t < T_DIM; t++) {
        const float v = g_dot[t * K2 + o];
        if (v >= THRESH) { cnt++; mask |= (1u << t); }
    }
    int first = T_DIM - cnt;
    if (first > T_DIM - 1) first = T_DIM - 1;
    const float fv    = g_dot[first * K2 + o];
    const float value = (fv < THRESH) ? 0.0f : fv;
    const float cand  = (cnt > 0) ? value : 0.0f;

    __shared__ float smx[K2];
    smx[o] = cand;
    __syncthreads();
    for (int s = K2 / 2; s > 0; s >>= 1) {
        if (o < s) smx[o] = fmaxf(smx[o], smx[o + s]);
        __syncthreads();
    }
    const float voff = smx[0] * (float)T_DIM;
    __syncthreads();

    __shared__ float tots[K2];
    __shared__ unsigned long long pk[K2];
    __shared__ unsigned char sel[K2];
    tots[o] = (cnt > 0) ? (float)cnt * (value + voff) : 0.0f;
    sel[o]  = 0;
    __syncthreads();

    for (int r = 0; r < 8; r++) {
        pk[o] = ((unsigned long long)__float_as_uint(tots[o]) << 32)
                | (unsigned)(K2 - 1 - o);
        __syncthreads();
        for (int s = K2 / 2; s > 0; s >>= 1) {
            if (o < s) { unsigned long long b = pk[o + s]; if (b > pk[o]) pk[o] = b; }
            __syncthreads();
        }
        if (o == 0) {
            const int idx = (K2 - 1) - (int)(unsigned)(pk[0] & 0xffffffffULL);
            if (tots[idx] != 0.0f) sel[idx] = 1;
            tots[idx] = 0.0f;
        }
        __syncthreads();
    }

#pragma unroll
    for (int t = 0; t < T_DIM; t++) {
        outp[t * K2 + o] = (sel[o] && ((mask >> t) & 1u)) ? 1.0f : 0.0f;
    }
}

// ---------------------------------------------------------------------------
extern "C" void kernel_launch(void* const* d_in, const int* in_sizes, int n_in,
                              void* d_out, int out_size)
{
    const float* rec = (const float*)d_in[0];   // (32,1,64,4096)
    const float* wgt = (const float*)d_in[1];   // (512,1,64,4096)
    if (n_in >= 2 && in_sizes[0] > in_sizes[1]) {
        const float* tmp = rec; rec = wgt; wgt = tmp;
    }
    float* outp = (float*)d_out;

    gemm_direct<<<dim3(4, KSPLIT), 256>>>(rec, wgt);
    reduce_kernel<<<T_DIM, K2>>>();
    post_kernel<<<1, K2>>>(outp);
}

// round 7
// speedup vs baseline: 2.9253x; 1.4290x over previous
#include <cuda_runtime.h>
#include <cuda_bf16.h>
#include <cstdint>
#include <cstddef>

#define T_DIM  32
#define K2     512
#define KD     262144
#define THRESH 0.2f

#define KSPLIT 74
#define KSLAB  32                          // fp32 k per pipeline stage
#define NSLAB_TOT (KD / KSLAB)             // 8192
#define SBASE (NSLAB_TOT / KSPLIT)         // 110
#define SREM  (NSLAB_TOT - SBASE * KSPLIT) // 52

#define STAGES   4
#define A_STRIDE 144                       // 128B data + 16B pad per W row
#define A_BYTES  (128 * A_STRIDE)          // 18432
#define B_STRIDE 80                        // 64B data + 16B pad per rec row
#define BH_OFF   A_BYTES
#define BL_OFF   (BH_OFF + 32 * B_STRIDE)
#define STAGE_BYTES (BL_OFF + 32 * B_STRIDE - BH_OFF + A_BYTES)  // 23552
#define SMEM_TOTAL  (STAGES * STAGE_BYTES)                       // 94208

__device__ __nv_bfloat16 g_rec_h[(size_t)T_DIM * KD];   // 16MB
__device__ __nv_bfloat16 g_rec_l[(size_t)T_DIM * KD];   // 16MB
__device__ float g_partial[(size_t)KSPLIT * T_DIM * K2];
__device__ float g_dot[T_DIM * K2];

// ---------------- helpers ----------------
__device__ __forceinline__ uint32_t smem_u32(const void* p) {
    uint32_t a;
    asm("{ .reg .u64 t; cvta.to.shared.u64 t, %1; cvt.u32.u64 %0, t; }"
        : "=r"(a) : "l"(p));
    return a;
}
__device__ __forceinline__ void cp16(uint32_t dst, const void* src) {
    asm volatile("cp.async.cg.shared.global [%0], [%1], 16;"
                 :: "r"(dst), "l"(src) : "memory");
}
__device__ __forceinline__ float2 lds64(uint32_t a) {
    float2 v;
    asm volatile("ld.shared.v2.f32 {%0,%1}, [%2];"
                 : "=f"(v.x), "=f"(v.y) : "r"(a));
    return v;
}
__device__ __forceinline__ void ldsm_x2(uint32_t* r, uint32_t addr) {
    asm volatile("ldmatrix.sync.aligned.m8n8.x2.shared.b16 {%0,%1}, [%2];"
                 : "=r"(r[0]), "=r"(r[1]) : "r"(addr));
}
__device__ __forceinline__ void mma_bf16(float* c, const uint32_t* a, const uint32_t* b) {
    asm volatile("mma.sync.aligned.m16n8k16.row.col.f32.bf16.bf16.f32 "
                 "{%0,%1,%2,%3}, {%4,%5,%6,%7}, {%8,%9}, {%0,%1,%2,%3};"
                 : "+f"(c[0]), "+f"(c[1]), "+f"(c[2]), "+f"(c[3])
                 : "r"(a[0]), "r"(a[1]), "r"(a[2]), "r"(a[3]),
                   "r"(b[0]), "r"(b[1]));
}
__device__ __forceinline__ void cvt2(float a, float b, uint32_t& h, uint32_t& l) {
    __nv_bfloat162 hb = __floats2bfloat162_rn(a, b);
    float2 hf = __bfloat1622float2(hb);
    __nv_bfloat162 lb = __floats2bfloat162_rn(a - hf.x, b - hf.y);
    h = *reinterpret_cast<uint32_t*>(&hb);
    l = *reinterpret_cast<uint32_t*>(&lb);
}

// ---------------------------------------------------------------------------
// pre-pass: split rec fp32 into bf16 hi/lo global arrays
// ---------------------------------------------------------------------------
__global__ void __launch_bounds__(256) split_rec(const float* __restrict__ rec)
{
    const size_t i = (size_t)blockIdx.x * 256 + threadIdx.x;  // float4 index
    const float4 v = reinterpret_cast<const float4*>(rec)[i];
    uint32_t h0, l0, h1, l1;
    cvt2(v.x, v.y, h0, l0);
    cvt2(v.z, v.w, h1, l1);
    uint2 hw; hw.x = h0; hw.y = h1;
    uint2 lw; lw.x = l0; lw.y = l1;
    reinterpret_cast<uint2*>(g_rec_h)[i] = hw;
    reinterpret_cast<uint2*>(g_rec_l)[i] = lw;
}

// ---------------------------------------------------------------------------
// cp.async-pipelined HMMA GEMM: partial[sp][t][o] = sum_k rec[t][k]*w[o][k]
// ---------------------------------------------------------------------------
__global__ void __launch_bounds__(256, 2)
gemm_pipe(const float* __restrict__ wgt)
{
    extern __shared__ __align__(128) char smem[];
    const uint32_t sbase = smem_u32(smem);

    const int tid = threadIdx.x;
    const int wid = tid >> 5;
    const int lid = tid & 31;
    const int g   = lid >> 2;
    const int tig = lid & 3;
    const int ot  = blockIdx.x;        // 0..3
    const int sp  = blockIdx.y;        // 0..73
    const int obase = ot * 128;

    const int s_begin = sp * SBASE + (sp < SREM ? sp : SREM);
    const int s_count = SBASE + (sp < SREM ? 1 : 0);

    // ---- staging maps ----
    // A: 4 x 16B transfers per thread (128 rows x 8 chunks)
    const float* asrc[4];
    uint32_t adst[4];
#pragma unroll
    for (int j = 0; j < 4; j++) {
        const int i = tid + 256 * j;
        const int arow = i >> 3, achk = i & 7;
        asrc[j] = wgt + (size_t)(obase + arow) * KD + achk * 4;
        adst[j] = sbase + (uint32_t)(arow * A_STRIDE + achk * 16);
    }
    // B: 1 x 16B transfer per thread (hi: tid<128, lo: tid>=128)
    const int brow = (tid & 127) >> 2, bchk = tid & 3;
    const __nv_bfloat16* bsrc =
        (tid < 128 ? g_rec_h : g_rec_l) + (size_t)brow * KD + bchk * 8;
    const uint32_t bdst = sbase + (uint32_t)((tid < 128 ? BH_OFF : BL_OFF)
                          + brow * B_STRIDE + bchk * 16);

#define ISSUE(S)                                                              \
    {   const uint32_t so = (uint32_t)((S) & 3) * STAGE_BYTES;                 \
        const size_t ko = (size_t)(s_begin + (S)) * KSLAB;                     \
        _Pragma("unroll") for (int j = 0; j < 4; j++)                          \
            cp16(adst[j] + so, asrc[j] + ko);                                  \
        cp16(bdst + so, bsrc + ko); }

    // ---- compute lane addresses ----
    const uint32_t a0b = sbase + (uint32_t)((wid * 16 + g) * A_STRIDE + tig * 8);
    const uint32_t a1b = a0b + 8 * A_STRIDE;
    const uint32_t bb  = sbase + (uint32_t)(BH_OFF + (lid & 7) * B_STRIDE
                          + ((lid >> 3) & 1) * 16);

    float acc[4][4];
#pragma unroll
    for (int nt = 0; nt < 4; nt++)
#pragma unroll
        for (int i = 0; i < 4; i++) acc[nt][i] = 0.0f;

    // prologue: 3 stages in flight
    ISSUE(0) asm volatile("cp.async.commit_group;" ::: "memory");
    ISSUE(1) asm volatile("cp.async.commit_group;" ::: "memory");
    ISSUE(2) asm volatile("cp.async.commit_group;" ::: "memory");

    for (int s = 0; s < s_count; s++) {
        asm volatile("cp.async.wait_group 2;" ::: "memory");
        __syncthreads();
        if (s + 3 < s_count) ISSUE(s + 3)
        asm volatile("cp.async.commit_group;" ::: "memory");

        const uint32_t so = (uint32_t)(s & 3) * STAGE_BYTES;
#pragma unroll
        for (int ks = 0; ks < 2; ks++) {
            const uint32_t ao = so + ks * 64;
            const float2 f0 = lds64(a0b + ao);
            const float2 f1 = lds64(a1b + ao);
            const float2 f2 = lds64(a0b + ao + 32);
            const float2 f3 = lds64(a1b + ao + 32);
            uint32_t Ah[4], Al[4];
            cvt2(f0.x, f0.y, Ah[0], Al[0]);
            cvt2(f1.x, f1.y, Ah[1], Al[1]);
            cvt2(f2.x, f2.y, Ah[2], Al[2]);
            cvt2(f3.x, f3.y, Ah[3], Al[3]);
            const uint32_t bo = bb + so + ks * 32;
#pragma unroll
            for (int nt = 0; nt < 4; nt++) {
                uint32_t Bh[2], Bl[2];
                ldsm_x2(Bh, bo + nt * (8 * B_STRIDE));
                ldsm_x2(Bl, bo + nt * (8 * B_STRIDE) + (BL_OFF - BH_OFF));
                mma_bf16(acc[nt], Ah, Bh);   // hh
                mma_bf16(acc[nt], Ah, Bl);   // hl
                mma_bf16(acc[nt], Al, Bh);   // lh
            }
        }
    }

    // epilogue: C frag (m16n8): c0=(g,2tig) c1=(g,2tig+1) c2=(g+8,..) c3
    const int orow = obase + wid * 16 + g;
#pragma unroll
    for (int nt = 0; nt < 4; nt++)
#pragma unroll
        for (int c = 0; c < 4; c++) {
            const int o = orow + ((c >> 1) ? 8 : 0);
            const int t = nt * 8 + 2 * tig + (c & 1);
            g_partial[((size_t)sp * T_DIM + t) * K2 + o] = acc[nt][c];
        }
}

// ---------------------------------------------------------------------------
// deterministic split-K reduction
// ---------------------------------------------------------------------------
__global__ void __launch_bounds__(512) reduce_kernel()
{
    const int t = blockIdx.x;
    const int o = threadIdx.x;
    const size_t stride = (size_t)T_DIM * K2;
    const size_t idx = (size_t)t * K2 + o;
    float s = 0.0f;
#pragma unroll
    for (int sp = 0; sp < KSPLIT; sp++)
        s += g_partial[(size_t)sp * stride + idx];
    g_dot[t * K2 + o] = s;
}

// ---------------------------------------------------------------------------
// post: threshold -> first-spike -> totals -> 8-round k-WTA -> binary output
// ---------------------------------------------------------------------------
__global__ void __launch_bounds__(512) post_kernel(float* __restrict__ outp)
{
    const int o = threadIdx.x;

    unsigned mask = 0;
    int cnt = 0;
#pragma unroll
    for (int t = 0; t < T_DIM; t++) {
        const float v = g_dot[t * K2 + o];
        if (v >= THRESH) { cnt++; mask |= (1u << t); }
    }
    int first = T_DIM - cnt;
    if (first > T_DIM - 1) first = T_DIM - 1;
    const float fv    = g_dot[first * K2 + o];
    const float value = (fv < THRESH) ? 0.0f : fv;
    const float cand  = (cnt > 0) ? value : 0.0f;

    __shared__ float smx[K2];
    smx[o] = cand;
    __syncthreads();
    for (int s = K2 / 2; s > 0; s >>= 1) {
        if (o < s) smx[o] = fmaxf(smx[o], smx[o + s]);
        __syncthreads();
    }
    const float voff = smx[0] * (float)T_DIM;
    __syncthreads();

    __shared__ float tots[K2];
    __shared__ unsigned long long pk[K2];
    __shared__ unsigned char sel[K2];
    tots[o] = (cnt > 0) ? (float)cnt * (value + voff) : 0.0f;
    sel[o]  = 0;
    __syncthreads();

    for (int r = 0; r < 8; r++) {
        pk[o] = ((unsigned long long)__float_as_uint(tots[o]) << 32)
                | (unsigned)(K2 - 1 - o);
        __syncthreads();
        for (int s = K2 / 2; s > 0; s >>= 1) {
            if (o < s) { unsigned long long b = pk[o + s]; if (b > pk[o]) pk[o] = b; }
            __syncthreads();
        }
        if (o == 0) {
            const int idx = (K2 - 1) - (int)(unsigned)(pk[0] & 0xffffffffULL);
            if (tots[idx] != 0.0f) sel[idx] = 1;
            tots[idx] = 0.0f;
        }
        __syncthreads();
    }

#pragma unroll
    for (int t = 0; t < T_DIM; t++) {
        outp[t * K2 + o] = (sel[o] && ((mask >> t) & 1u)) ? 1.0f : 0.0f;
    }
}

// ---------------------------------------------------------------------------
extern "C" void kernel_launch(void* const* d_in, const int* in_sizes, int n_in,
                              void* d_out, int out_size)
{
    const float* rec = (const float*)d_in[0];   // (32,1,64,4096)
    const float* wgt = (const float*)d_in[1];   // (512,1,64,4096)
    if (n_in >= 2 && in_sizes[0] > in_sizes[1]) {
        const float* tmp = rec; rec = wgt; wgt = tmp;
    }
    float* outp = (float*)d_out;

    cudaFuncSetAttribute(gemm_pipe, cudaFuncAttributeMaxDynamicSharedMemorySize,
                         SMEM_TOTAL);

    split_rec<<<(T_DIM * KD / 4) / 256, 256>>>(rec);
    gemm_pipe<<<dim3(4, KSPLIT), 256, SMEM_TOTAL>>>(wgt);
    reduce_kernel<<<T_DIM, K2>>>();
    post_kernel<<<1, K2>>>(outp);
}